// round 5
// baseline (speedup 1.0000x reference)
#include <cuda_runtime.h>
#include <cuda_bf16.h>
#include <math.h>
#include <stdint.h>

#define WIDTH 128
#define NMAX  50176
#define EMAX  512000
#define TILEB 32768                       // one 128x128 bf16 tile image
#define DSTRIDE 132                       // staging row stride (floats)
#define DSMEM (4 * TILEB + 128 * DSTRIDE * 4)   // 198656 bytes

// ---- scratch (device globals) ----
__device__ float g_Q [NMAX * WIDTH];
__device__ float g_K [NMAX * WIDTH];
__device__ float g_V [NMAX * WIDTH];
__device__ float g_X2[NMAX * WIDTH];
__device__ float g_T  [3 * 34 * WIDTH];
__device__ float g_T81[81 * 3 * WIDTH];       // [idx][j][128]
__device__ unsigned char g_iW[6][2][TILEB];   // weight images (n x k), hi/lo
__device__ int g_cnt [NMAX];
__device__ int g_cur [NMAX];
__device__ int g_base[NMAX + 1];
__device__ int g_esrc[EMAX];
__device__ int g_eidx[EMAX];

__device__ __forceinline__ float gelu1(float x) {
    return 0.5f * x * (1.0f + erff(x * 0.7071067811865475f));
}
__device__ __forceinline__ float gelu_t(float x) {
    float u = 0.7978845608028654f * fmaf(0.044715f * x, x * x, x);
    float t;
    asm("tanh.approx.f32 %0, %1;" : "=f"(t) : "f"(u));
    return 0.5f * x * (1.0f + t);
}

// XOR-swizzled offset for a 128-row x 16-chunk (16B chunks) bf16 tile.
__device__ __forceinline__ int soff(int row, int kc) {
    return row * 256 + ((kc ^ (row & 7)) << 4);
}

__device__ __forceinline__ uint32_t smem_u32(const void* p) {
    uint32_t a;
    asm("{ .reg .u64 t; cvta.to.shared.u64 t, %1; cvt.u32.u64 %0, t; }" : "=r"(a) : "l"(p));
    return a;
}
__device__ __forceinline__ void ldm4(uint32_t* r, uint32_t a) {
    asm volatile("ldmatrix.sync.aligned.m8n8.x4.shared.b16 {%0,%1,%2,%3}, [%4];"
                 : "=r"(r[0]), "=r"(r[1]), "=r"(r[2]), "=r"(r[3]) : "r"(a));
}
__device__ __forceinline__ void mma16816(float* c, const uint32_t* a, uint32_t b0, uint32_t b1) {
    asm volatile(
        "mma.sync.aligned.m16n8k16.row.col.f32.bf16.bf16.f32 "
        "{%0,%1,%2,%3}, {%4,%5,%6,%7}, {%8,%9}, {%0,%1,%2,%3};"
        : "+f"(c[0]), "+f"(c[1]), "+f"(c[2]), "+f"(c[3])
        : "r"(a[0]), "r"(a[1]), "r"(a[2]), "r"(a[3]), "r"(b0), "r"(b1));
}

// ============================================================================
// Tables
// ============================================================================
__global__ void k_tables(const float* __restrict__ r0w, const float* __restrict__ r1w,
                         const float* __restrict__ r2w,
                         const float* __restrict__ e0, const float* __restrict__ e1,
                         const float* __restrict__ e2, const float* __restrict__ e3,
                         const float* __restrict__ einit, const float* __restrict__ init0)
{
    int j = blockIdx.x, r = blockIdx.y, o = threadIdx.x;
    int c, lr;
    if (r < 6)       { c = 0; lr = r; }
    else if (r < 13) { c = 1; lr = r - 6; }
    else if (r < 16) { c = 2; lr = r - 13; }
    else             { c = 3; lr = r - 16; }
    const float* emb = (c == 0) ? e0 : (c == 1) ? e1 : (c == 2) ? e2 : e3;
    const float* rw  = (j == 0) ? r0w : (j == 1) ? r1w : r2w;

    __shared__ float er[64];
    if (o < 64) er[o] = emb[lr * 64 + o];
    __syncthreads();

    float s = 0.0f;
#pragma unroll
    for (int m = 0; m < 64; m++) s += er[m] * rw[m * WIDTH + o];

    float es = expf(einit[0]) + expf(einit[1]) + expf(einit[2]) + expf(einit[3]);
    float xw = expf(einit[c]) * rsqrtf(es);
    float sf = expf((j == 2) ? init0[3] : init0[2]);
    g_T[(j * 34 + r) * WIDTH + o] = s * xw * sf;
}

// Combined [81][3][128] tables
__global__ void k_combine()
{
    int j = blockIdx.x, i = blockIdx.y, o = threadIdx.x;
    int d0 = i % 3, d1 = (i / 3) % 3, d2 = (i / 9) % 3, d3 = i / 27;
    g_T81[(i * 3 + j) * WIDTH + o] =
        g_T[(j * 34 + d0) * WIDTH + o] + g_T[(j * 34 + 6 + d1) * WIDTH + o] +
        g_T[(j * 34 + 13 + d2) * WIDTH + o] + g_T[(j * 34 + 16 + d3) * WIDTH + o];
}

// ============================================================================
// CSR build: zero -> histogram -> scan -> scatter
// ============================================================================
__global__ void k_zero(int n)
{
    int i = blockIdx.x * blockDim.x + threadIdx.x;
    if (i < n) { g_cnt[i] = 0; g_cur[i] = 0; }
}
__global__ void k_hist(const int* __restrict__ ei, int e)
{
    for (int i = blockIdx.x * blockDim.x + threadIdx.x; i < e; i += gridDim.x * blockDim.x)
        atomicAdd(&g_cnt[ei[e + i]], 1);
}
__global__ void __launch_bounds__(1024) k_scan(int n, int e)
{
    __shared__ int sp[1024];
    int t = threadIdx.x;
    int chunk = (n + 1023) >> 10;
    int lo = t * chunk, hi = min(lo + chunk, n);
    int s = 0;
    for (int i = lo; i < hi; i++) s += g_cnt[i];
    sp[t] = s;
    __syncthreads();
    for (int d = 1; d < 1024; d <<= 1) {
        int v = (t >= d) ? sp[t - d] : 0;
        __syncthreads();
        if (t >= d) sp[t] += v;
        __syncthreads();
    }
    int run = (t > 0) ? sp[t - 1] : 0;
    for (int i = lo; i < hi; i++) { int c = g_cnt[i]; g_base[i] = run; run += c; }
    if (t == 0) g_base[n] = e;
}
__global__ void k_scatter(const int* __restrict__ ei, const int* __restrict__ ea, int e)
{
    for (int i = blockIdx.x * blockDim.x + threadIdx.x; i < e; i += gridDim.x * blockDim.x) {
        int dst = ei[e + i];
        int4 a = __ldg((const int4*)ea + i);
        int idx = a.x + 3 * a.y + 9 * a.z + 27 * a.w;
        int pos = g_base[dst] + atomicAdd(&g_cur[dst], 1);
        g_esrc[pos] = ei[i];
        g_eidx[pos] = idx;
    }
}

// ============================================================================
// Weight prep: Bt[n][k] = W[k][n], bf16 hi/lo, swizzled image.
// ============================================================================
__global__ void __launch_bounds__(256) k_prepw(const float* __restrict__ w0,
    const float* __restrict__ w1, const float* __restrict__ w2,
    const float* __restrict__ w3, const float* __restrict__ w4,
    const float* __restrict__ w5)
{
    int wi = blockIdx.x >> 3, sl = blockIdx.x & 7;
    const float* W = (wi == 0) ? w0 : (wi == 1) ? w1 : (wi == 2) ? w2
                   : (wi == 3) ? w3 : (wi == 4) ? w4 : w5;
    int nrow = sl * 16 + (threadIdx.x >> 4);
    int kc = threadIdx.x & 15;
    __nv_bfloat16 h8[8], l8[8];
#pragma unroll
    for (int j = 0; j < 8; j++) {
        float v = W[(kc * 8 + j) * WIDTH + nrow];   // transpose read
        h8[j] = __float2bfloat16(v);
        l8[j] = __float2bfloat16(v - __bfloat162float(h8[j]));
    }
    int off = soff(nrow, kc);
    *(uint4*)(g_iW[wi][0] + off) = *(uint4*)h8;
    *(uint4*)(g_iW[wi][1] + off) = *(uint4*)l8;
}

// ============================================================================
// mma.sync GEMM, 128x128 tile, fp32-accurate via bf16 hi/lo (3 passes).
// mode 0: PRE+QKVM fused. steps: pre(LN->rebuild A image), then Q,K,V,X2.
// mode 2: POST (residual -> dout).
// ============================================================================
__global__ void __launch_bounds__(256, 1)
k_mma(int mode, const float* __restrict__ x,
      const float* __restrict__ pre_b, const float* __restrict__ post_b,
      const float* __restrict__ m0b, const float* __restrict__ m1b,
      const float* __restrict__ m2b, const float* __restrict__ m3b,
      const float* __restrict__ r0b, const float* __restrict__ r1b,
      const float* __restrict__ r2b,
      const float* __restrict__ init0, float* __restrict__ dout, int n)
{
    extern __shared__ unsigned char sm[];
    const uint32_t sbase = smem_u32(sm);
    const uint32_t sAh = sbase, sAl = sbase + TILEB;
    const uint32_t sBh = sbase + 2 * TILEB, sBl = sbase + 3 * TILEB;
    float* Dst = (float*)(sm + 4 * TILEB);

    const int tid = threadIdx.x;
    const int wid = tid >> 5, lane = tid & 31;
    const int wr = wid >> 1, wc = wid & 1;
    const int tile = blockIdx.x, r0 = tile * 128;

    // ---- A tile: fp32 -> bf16 hi/lo, swizzled smem ----
    const float* Asrc = (mode == 0) ? x : g_X2;
#pragma unroll
    for (int it = 0; it < 8; it++) {
        int c = tid + it * 256;
        int row = c >> 4, kc = c & 15;
        int gr = r0 + row;
        float v[8];
        if (gr < n) {
            float4 a = *(const float4*)&Asrc[gr * WIDTH + kc * 8];
            float4 b = *(const float4*)&Asrc[gr * WIDTH + kc * 8 + 4];
            v[0] = a.x; v[1] = a.y; v[2] = a.z; v[3] = a.w;
            v[4] = b.x; v[5] = b.y; v[6] = b.z; v[7] = b.w;
        } else {
#pragma unroll
            for (int j = 0; j < 8; j++) v[j] = 0.0f;
        }
        __nv_bfloat16 h8[8], l8[8];
#pragma unroll
        for (int j = 0; j < 8; j++) {
            h8[j] = __float2bfloat16(v[j]);
            l8[j] = __float2bfloat16(v[j] - __bfloat162float(h8[j]));
        }
        int off = soff(row, kc);
        *(uint4*)(sm + off) = *(uint4*)h8;
        *(uint4*)(sm + TILEB + off) = *(uint4*)l8;
    }

    const int nsteps = (mode == 0) ? 5 : 1;
    for (int step = 0; step < nsteps; step++) {
        int widx = (mode == 0) ? step : 5;
        // copy weight images into smem
        {
            const uint4* sh = (const uint4*)g_iW[widx][0];
            const uint4* sl = (const uint4*)g_iW[widx][1];
            uint4* dh = (uint4*)(sm + 2 * TILEB);
            uint4* dl = (uint4*)(sm + 3 * TILEB);
#pragma unroll
            for (int i = 0; i < 8; i++) { dh[tid + i * 256] = sh[tid + i * 256];
                                          dl[tid + i * 256] = sl[tid + i * 256]; }
        }
        __syncthreads();

        float acc[2][8][4];
#pragma unroll
        for (int i = 0; i < 2; i++)
#pragma unroll
            for (int j = 0; j < 8; j++)
#pragma unroll
                for (int q = 0; q < 4; q++) acc[i][j][q] = 0.0f;

#pragma unroll
        for (int pass = 0; pass < 3; pass++) {
            uint32_t Ab = (pass == 2) ? sAl : sAh;
            uint32_t Bb = (pass == 1) ? sBl : sBh;
#pragma unroll
            for (int kk = 0; kk < 8; kk++) {
                uint32_t a[2][4], b[4][4];
#pragma unroll
                for (int mt = 0; mt < 2; mt++) {
                    int row = wr * 32 + mt * 16 + (lane & 15);
                    int kc = 2 * kk + (lane >> 4);
                    ldm4(a[mt], Ab + soff(row, kc));
                }
#pragma unroll
                for (int nt = 0; nt < 4; nt++) {
                    int nn = wc * 64 + nt * 16 + (lane & 7) + ((lane >> 4) << 3);
                    int kc = 2 * kk + ((lane >> 3) & 1);
                    ldm4(b[nt], Bb + soff(nn, kc));
                }
#pragma unroll
                for (int mt = 0; mt < 2; mt++)
#pragma unroll
                    for (int nt = 0; nt < 4; nt++) {
                        mma16816(acc[mt][2 * nt],     a[mt], b[nt][0], b[nt][1]);
                        mma16816(acc[mt][2 * nt + 1], a[mt], b[nt][2], b[nt][3]);
                    }
            }
        }
        __syncthreads();

        // ---- stage D fragments to padded smem ----
#pragma unroll
        for (int mt = 0; mt < 2; mt++)
#pragma unroll
            for (int j = 0; j < 8; j++) {
                int row = wr * 32 + mt * 16 + (lane >> 2);
                int col = wc * 64 + j * 8 + 2 * (lane & 3);
                Dst[row * DSTRIDE + col]           = acc[mt][j][0];
                Dst[row * DSTRIDE + col + 1]       = acc[mt][j][1];
                Dst[(row + 8) * DSTRIDE + col]     = acc[mt][j][2];
                Dst[(row + 8) * DSTRIDE + col + 1] = acc[mt][j][3];
            }
        __syncthreads();

        if (mode == 0 && step == 0) {
            // PRE epilogue: bias + LN, write LN'd rows back to Dst
            float4 bb = __ldg((const float4*)&pre_b[lane * 4]);
#pragma unroll
            for (int r = 0; r < 16; r++) {
                int row = wid * 16 + r;
                float4 v = *(float4*)&Dst[row * DSTRIDE + lane * 4];
                v.x += bb.x; v.y += bb.y; v.z += bb.z; v.w += bb.w;
                float s1 = v.x + v.y + v.z + v.w;
                float s2 = v.x * v.x + v.y * v.y + v.z * v.z + v.w * v.w;
#pragma unroll
                for (int m = 16; m; m >>= 1) {
                    s1 += __shfl_xor_sync(0xffffffffu, s1, m);
                    s2 += __shfl_xor_sync(0xffffffffu, s2, m);
                }
                float mean = s1 * (1.0f / 128.0f);
                float var  = s2 * (1.0f / 128.0f) - mean * mean;
                float rstd = rsqrtf(var + 1e-5f);
                float4 o = make_float4((v.x - mean) * rstd, (v.y - mean) * rstd,
                                       (v.z - mean) * rstd, (v.w - mean) * rstd);
                *(float4*)&Dst[row * DSTRIDE + lane * 4] = o;
            }
            __syncthreads();
            // rebuild A image from LN'd Dst
#pragma unroll
            for (int it = 0; it < 8; it++) {
                int c = tid + it * 256;
                int row = c >> 4, kc = c & 15;
                float4 a = *(float4*)&Dst[row * DSTRIDE + kc * 8];
                float4 b = *(float4*)&Dst[row * DSTRIDE + kc * 8 + 4];
                float v[8] = {a.x, a.y, a.z, a.w, b.x, b.y, b.z, b.w};
                __nv_bfloat16 h8[8], l8[8];
#pragma unroll
                for (int j = 0; j < 8; j++) {
                    h8[j] = __float2bfloat16(v[j]);
                    l8[j] = __float2bfloat16(v[j] - __bfloat162float(h8[j]));
                }
                int off = soff(row, kc);
                *(uint4*)(sm + off) = *(uint4*)h8;
                *(uint4*)(sm + TILEB + off) = *(uint4*)l8;
            }
        } else if (mode == 0) {
            int iw = step - 1;
            const float* b1; const float* b2; float* out; float sc; int dg = 0;
            float sc_e = expf(init0[2]);
            float sc_v = expf(init0[3]);
            if (iw == 0)      { b1 = m1b; b2 = r0b; sc = sc_e; out = g_Q; }
            else if (iw == 1) { b1 = m2b; b2 = r1b; sc = sc_e; out = g_K; }
            else if (iw == 2) { b1 = m3b; b2 = r2b; sc = sc_v; out = g_V; }
            else              { b1 = m0b; b2 = 0;   sc = 0.f;  out = g_X2; dg = 1; }
            float4 bb = __ldg((const float4*)&b1[lane * 4]);
            if (b2) {
                float4 b2v = __ldg((const float4*)&b2[lane * 4]);
                bb.x += sc * b2v.x; bb.y += sc * b2v.y;
                bb.z += sc * b2v.z; bb.w += sc * b2v.w;
            }
#pragma unroll
            for (int r = 0; r < 16; r++) {
                int row = wid * 16 + r;
                int gr = r0 + row;
                if (gr >= n) continue;
                float4 v = *(float4*)&Dst[row * DSTRIDE + lane * 4];
                v.x += bb.x; v.y += bb.y; v.z += bb.z; v.w += bb.w;
                if (dg) { v.x = gelu1(v.x); v.y = gelu1(v.y);
                          v.z = gelu1(v.z); v.w = gelu1(v.w); }
                *(float4*)&out[gr * WIDTH + lane * 4] = v;
            }
        } else {
            float4 bb = __ldg((const float4*)&post_b[lane * 4]);
#pragma unroll
            for (int r = 0; r < 16; r++) {
                int row = wid * 16 + r;
                int gr = r0 + row;
                if (gr >= n) continue;
                float4 v = *(float4*)&Dst[row * DSTRIDE + lane * 4];
                float4 xv = __ldg((const float4*)&x[gr * WIDTH + lane * 4]);
                float4 o = make_float4(v.x + bb.x + xv.x, v.y + bb.y + xv.y,
                                       v.z + bb.z + xv.z, v.w + bb.w + xv.w);
                *(float4*)&dout[gr * WIDTH + lane * 4] = o;
            }
        }
        __syncthreads();
    }
}

// ============================================================================
// Edge phase: one warp per destination node over its CSR segment.
// X2[v] += sum_j gelu(V[src_j]+T2[idx_j]) * att_j  -- no atomics.
// ============================================================================
__global__ void __launch_bounds__(256) k_edge2(const float* __restrict__ init0, int n)
{
    int v = blockIdx.x * 8 + (threadIdx.x >> 5);
    if (v >= n) return;
    int lane = threadIdx.x & 31;
    int b0 = g_base[v], b1 = g_base[v + 1];
    if (b0 == b1) return;

    int c4 = lane << 2;
    float4 Qv = *(const float4*)&g_Q[v * WIDTH + c4];
    float sA = init0[0] * 0.125f;
    float sB = init0[1];
    float4 acc = make_float4(0.f, 0.f, 0.f, 0.f);
    const float4* T = (const float4*)g_T81;

    for (int j = b0; j < b1; j++) {
        int src = __ldg(&g_esrc[j]);
        int idx = __ldg(&g_eidx[j]);
        float4 t0 = __ldg(&T[(idx * 3 + 0) * 32 + lane]);
        float4 t1 = __ldg(&T[(idx * 3 + 1) * 32 + lane]);
        float4 t2 = __ldg(&T[(idx * 3 + 2) * 32 + lane]);
        float4 kv = __ldg((const float4*)&g_K[src * WIDTH + c4]);
        float4 vv = __ldg((const float4*)&g_V[src * WIDTH + c4]);

        float s = (Qv.x + t0.x) * (kv.x + t1.x) + (Qv.y + t0.y) * (kv.y + t1.y)
                + (Qv.z + t0.z) * (kv.z + t1.z) + (Qv.w + t0.w) * (kv.w + t1.w);
#pragma unroll
        for (int m = 8; m; m >>= 1) s += __shfl_xor_sync(0xffffffffu, s, m);
        // lanes 0-15: head0, lanes 16-31: head1

        float att = __expf(fmaf(s, sA, sB));
        acc.x = fmaf(gelu_t(vv.x + t2.x), att, acc.x);
        acc.y = fmaf(gelu_t(vv.y + t2.y), att, acc.y);
        acc.z = fmaf(gelu_t(vv.z + t2.z), att, acc.z);
        acc.w = fmaf(gelu_t(vv.w + t2.w), att, acc.w);
    }

    float* xp = &g_X2[v * WIDTH + c4];
    float4 cur = *(float4*)xp;
    cur.x += acc.x; cur.y += acc.y; cur.z += acc.z; cur.w += acc.w;
    *(float4*)xp = cur;
}

extern "C" void kernel_launch(void* const* d_in, const int* in_sizes, int n_in,
                              void* d_out, int out_size)
{
    const float* x        = (const float*)d_in[0];
    const int*   ei       = (const int*)  d_in[1];
    const int*   ea       = (const int*)  d_in[2];
    const float* pre_w    = (const float*)d_in[3];
    const float* pre_b    = (const float*)d_in[4];
    const float* msg0_w   = (const float*)d_in[5];
    const float* msg0_b   = (const float*)d_in[6];
    const float* msg1_w   = (const float*)d_in[7];
    const float* msg1_b   = (const float*)d_in[8];
    const float* msg2_w   = (const float*)d_in[9];
    const float* msg2_b   = (const float*)d_in[10];
    const float* msg3_w   = (const float*)d_in[11];
    const float* msg3_b   = (const float*)d_in[12];
    const float* remix0_w = (const float*)d_in[13];
    const float* remix0_b = (const float*)d_in[14];
    const float* remix1_w = (const float*)d_in[15];
    const float* remix1_b = (const float*)d_in[16];
    const float* remix2_w = (const float*)d_in[17];
    const float* remix2_b = (const float*)d_in[18];
    const float* post_w   = (const float*)d_in[19];
    const float* post_b   = (const float*)d_in[20];
    const float* emb0     = (const float*)d_in[21];
    const float* emb1     = (const float*)d_in[22];
    const float* emb2     = (const float*)d_in[23];
    const float* emb3     = (const float*)d_in[24];
    const float* einit    = (const float*)d_in[25];
    const float* init0    = (const float*)d_in[26];

    int n = in_sizes[0] / WIDTH;
    int e = in_sizes[1] / 2;
    int nt = (n + 127) / 128;

    static int smem_set = 0;
    if (!smem_set) {
        cudaFuncSetAttribute(k_mma, cudaFuncAttributeMaxDynamicSharedMemorySize, DSMEM);
        smem_set = 1;
    }

    k_prepw<<<48, 256>>>(pre_w, msg1_w, msg2_w, msg3_w, msg0_w, post_w);

    dim3 tg(3, 34);
    k_tables<<<tg, 128>>>(remix0_w, remix1_w, remix2_w, emb0, emb1, emb2, emb3, einit, init0);
    dim3 cg(3, 81);
    k_combine<<<cg, 128>>>();

    // CSR build
    k_zero<<<(n + 255) / 256, 256>>>(n);
    k_hist<<<512, 256>>>(ei, e);
    k_scan<<<1, 1024>>>(n, e);
    k_scatter<<<512, 256>>>(ei, ea, e);

    // PRE + QKVM fused
    k_mma<<<nt, 256, DSMEM>>>(0, x, pre_b, post_b, msg0_b, msg1_b, msg2_b, msg3_b,
                              remix0_b, remix1_b, remix2_b, init0, (float*)d_out, n);

    // edge aggregation (CSR, warp per node)
    k_edge2<<<(n + 7) / 8, 256>>>(init0, n);

    // POST: out = x + X2 @ post_w + post_b
    k_mma<<<nt, 256, DSMEM>>>(2, x, pre_b, post_b, msg0_b, msg1_b, msg2_b, msg3_b,
                              remix0_b, remix1_b, remix2_b, init0, (float*)d_out, n);
}

// round 6
// speedup vs baseline: 1.5168x; 1.5168x over previous
#include <cuda_runtime.h>
#include <cuda_bf16.h>
#include <math.h>
#include <stdint.h>

#define WIDTH 128
#define NMAX  50176
#define TILEB 32768                       // one 128x128 bf16 tile image
#define DSTRIDE 132                       // staging row stride (floats)
#define DSMEM (4 * TILEB + 128 * DSTRIDE * 4)   // 198656 bytes

// ---- scratch (device globals) ----
__device__ float g_Q [NMAX * WIDTH];
__device__ float g_K [NMAX * WIDTH];
__device__ float g_V [NMAX * WIDTH];
__device__ float g_X2[NMAX * WIDTH];
__device__ float g_T  [3 * 34 * WIDTH];
__device__ float g_T81[81 * 3 * WIDTH];       // [idx][j][128]
__device__ unsigned char g_iW[6][2][TILEB];   // weight images (n x k), hi/lo

__device__ __forceinline__ float gelu1(float x) {
    return 0.5f * x * (1.0f + erff(x * 0.7071067811865475f));
}
__device__ __forceinline__ float gelu_t(float x) {
    float u = 0.7978845608028654f * fmaf(0.044715f * x, x * x, x);
    float t;
    asm("tanh.approx.f32 %0, %1;" : "=f"(t) : "f"(u));
    return 0.5f * x * (1.0f + t);
}

// XOR-swizzled offset for a 128-row x 16-chunk (16B chunks) bf16 tile.
__device__ __forceinline__ int soff(int row, int kc) {
    return row * 256 + ((kc ^ (row & 7)) << 4);
}

__device__ __forceinline__ uint32_t smem_u32(const void* p) {
    uint32_t a;
    asm("{ .reg .u64 t; cvta.to.shared.u64 t, %1; cvt.u32.u64 %0, t; }" : "=r"(a) : "l"(p));
    return a;
}
__device__ __forceinline__ void ldm4(uint32_t* r, uint32_t a) {
    asm volatile("ldmatrix.sync.aligned.m8n8.x4.shared.b16 {%0,%1,%2,%3}, [%4];"
                 : "=r"(r[0]), "=r"(r[1]), "=r"(r[2]), "=r"(r[3]) : "r"(a));
}
__device__ __forceinline__ void mma16816(float* c, const uint32_t* a, uint32_t b0, uint32_t b1) {
    asm volatile(
        "mma.sync.aligned.m16n8k16.row.col.f32.bf16.bf16.f32 "
        "{%0,%1,%2,%3}, {%4,%5,%6,%7}, {%8,%9}, {%0,%1,%2,%3};"
        : "+f"(c[0]), "+f"(c[1]), "+f"(c[2]), "+f"(c[3])
        : "r"(a[0]), "r"(a[1]), "r"(a[2]), "r"(a[3]), "r"(b0), "r"(b1));
}

// ============================================================================
// Tables
// ============================================================================
__global__ void k_tables(const float* __restrict__ r0w, const float* __restrict__ r1w,
                         const float* __restrict__ r2w,
                         const float* __restrict__ e0, const float* __restrict__ e1,
                         const float* __restrict__ e2, const float* __restrict__ e3,
                         const float* __restrict__ einit, const float* __restrict__ init0)
{
    int j = blockIdx.x, r = blockIdx.y, o = threadIdx.x;
    int c, lr;
    if (r < 6)       { c = 0; lr = r; }
    else if (r < 13) { c = 1; lr = r - 6; }
    else if (r < 16) { c = 2; lr = r - 13; }
    else             { c = 3; lr = r - 16; }
    const float* emb = (c == 0) ? e0 : (c == 1) ? e1 : (c == 2) ? e2 : e3;
    const float* rw  = (j == 0) ? r0w : (j == 1) ? r1w : r2w;

    __shared__ float er[64];
    if (o < 64) er[o] = emb[lr * 64 + o];
    __syncthreads();

    float s = 0.0f;
#pragma unroll
    for (int m = 0; m < 64; m++) s += er[m] * rw[m * WIDTH + o];

    float es = expf(einit[0]) + expf(einit[1]) + expf(einit[2]) + expf(einit[3]);
    float xw = expf(einit[c]) * rsqrtf(es);
    float sf = expf((j == 2) ? init0[3] : init0[2]);
    g_T[(j * 34 + r) * WIDTH + o] = s * xw * sf;
}

// Combined [81][3][128] tables
__global__ void k_combine()
{
    int j = blockIdx.x, i = blockIdx.y, o = threadIdx.x;
    int d0 = i % 3, d1 = (i / 3) % 3, d2 = (i / 9) % 3, d3 = i / 27;
    g_T81[(i * 3 + j) * WIDTH + o] =
        g_T[(j * 34 + d0) * WIDTH + o] + g_T[(j * 34 + 6 + d1) * WIDTH + o] +
        g_T[(j * 34 + 13 + d2) * WIDTH + o] + g_T[(j * 34 + 16 + d3) * WIDTH + o];
}

// ============================================================================
// Weight prep: Bt[n][k] = W[k][n], bf16 hi/lo, swizzled image.
// ============================================================================
__global__ void __launch_bounds__(256) k_prepw(const float* __restrict__ w0,
    const float* __restrict__ w1, const float* __restrict__ w2,
    const float* __restrict__ w3, const float* __restrict__ w4,
    const float* __restrict__ w5)
{
    int wi = blockIdx.x >> 3, sl = blockIdx.x & 7;
    const float* W = (wi == 0) ? w0 : (wi == 1) ? w1 : (wi == 2) ? w2
                   : (wi == 3) ? w3 : (wi == 4) ? w4 : w5;
    int nrow = sl * 16 + (threadIdx.x >> 4);
    int kc = threadIdx.x & 15;
    __nv_bfloat16 h8[8], l8[8];
#pragma unroll
    for (int j = 0; j < 8; j++) {
        float v = W[(kc * 8 + j) * WIDTH + nrow];   // transpose read
        h8[j] = __float2bfloat16(v);
        l8[j] = __float2bfloat16(v - __bfloat162float(h8[j]));
    }
    int off = soff(nrow, kc);
    *(uint4*)(g_iW[wi][0] + off) = *(uint4*)h8;
    *(uint4*)(g_iW[wi][1] + off) = *(uint4*)l8;
}

// ============================================================================
// mma.sync GEMM, 128x128 tile, fp32-accurate via bf16 hi/lo (3 passes).
// mode 0: PRE+QKVM fused. steps: pre(LN->rebuild A image), Q, K, V, X2.
//         When init0[0] == 0 the Q/K steps are skipped (att is constant).
// mode 2: POST (residual -> dout).
// ============================================================================
__global__ void __launch_bounds__(256, 1)
k_mma(int mode, const float* __restrict__ x,
      const float* __restrict__ pre_b, const float* __restrict__ post_b,
      const float* __restrict__ m0b, const float* __restrict__ m1b,
      const float* __restrict__ m2b, const float* __restrict__ m3b,
      const float* __restrict__ r0b, const float* __restrict__ r1b,
      const float* __restrict__ r2b,
      const float* __restrict__ init0, float* __restrict__ dout, int n)
{
    extern __shared__ unsigned char sm[];
    const uint32_t sbase = smem_u32(sm);
    const uint32_t sAh = sbase, sAl = sbase + TILEB;
    const uint32_t sBh = sbase + 2 * TILEB, sBl = sbase + 3 * TILEB;
    float* Dst = (float*)(sm + 4 * TILEB);

    const int tid = threadIdx.x;
    const int wid = tid >> 5, lane = tid & 31;
    const int wr = wid >> 1, wc = wid & 1;
    const int tile = blockIdx.x, r0 = tile * 128;
    const int skipQK = (mode == 0) && (__ldg(&init0[0]) == 0.0f);

    // ---- A tile: fp32 -> bf16 hi/lo, swizzled smem ----
    const float* Asrc = (mode == 0) ? x : g_X2;
#pragma unroll
    for (int it = 0; it < 8; it++) {
        int c = tid + it * 256;
        int row = c >> 4, kc = c & 15;
        int gr = r0 + row;
        float v[8];
        if (gr < n) {
            float4 a = *(const float4*)&Asrc[gr * WIDTH + kc * 8];
            float4 b = *(const float4*)&Asrc[gr * WIDTH + kc * 8 + 4];
            v[0] = a.x; v[1] = a.y; v[2] = a.z; v[3] = a.w;
            v[4] = b.x; v[5] = b.y; v[6] = b.z; v[7] = b.w;
        } else {
#pragma unroll
            for (int j = 0; j < 8; j++) v[j] = 0.0f;
        }
        __nv_bfloat16 h8[8], l8[8];
#pragma unroll
        for (int j = 0; j < 8; j++) {
            h8[j] = __float2bfloat16(v[j]);
            l8[j] = __float2bfloat16(v[j] - __bfloat162float(h8[j]));
        }
        int off = soff(row, kc);
        *(uint4*)(sm + off) = *(uint4*)h8;
        *(uint4*)(sm + TILEB + off) = *(uint4*)l8;
    }

    const int nsteps = (mode == 0) ? 5 : 1;
    for (int step = 0; step < nsteps; step++) {
        if (skipQK && (step == 1 || step == 2)) continue;   // uniform branch
        int widx = (mode == 0) ? step : 5;
        // copy weight images into smem
        {
            const uint4* sh = (const uint4*)g_iW[widx][0];
            const uint4* sl = (const uint4*)g_iW[widx][1];
            uint4* dh = (uint4*)(sm + 2 * TILEB);
            uint4* dl = (uint4*)(sm + 3 * TILEB);
#pragma unroll
            for (int i = 0; i < 8; i++) { dh[tid + i * 256] = sh[tid + i * 256];
                                          dl[tid + i * 256] = sl[tid + i * 256]; }
        }
        __syncthreads();

        float acc[2][8][4];
#pragma unroll
        for (int i = 0; i < 2; i++)
#pragma unroll
            for (int j = 0; j < 8; j++)
#pragma unroll
                for (int q = 0; q < 4; q++) acc[i][j][q] = 0.0f;

#pragma unroll
        for (int pass = 0; pass < 3; pass++) {
            uint32_t Ab = (pass == 2) ? sAl : sAh;
            uint32_t Bb = (pass == 1) ? sBl : sBh;
#pragma unroll
            for (int kk = 0; kk < 8; kk++) {
                uint32_t a[2][4], b[4][4];
#pragma unroll
                for (int mt = 0; mt < 2; mt++) {
                    int row = wr * 32 + mt * 16 + (lane & 15);
                    int kc = 2 * kk + (lane >> 4);
                    ldm4(a[mt], Ab + soff(row, kc));
                }
#pragma unroll
                for (int nt = 0; nt < 4; nt++) {
                    int nn = wc * 64 + nt * 16 + (lane & 7) + ((lane >> 4) << 3);
                    int kc = 2 * kk + ((lane >> 3) & 1);
                    ldm4(b[nt], Bb + soff(nn, kc));
                }
#pragma unroll
                for (int mt = 0; mt < 2; mt++)
#pragma unroll
                    for (int nt = 0; nt < 4; nt++) {
                        mma16816(acc[mt][2 * nt],     a[mt], b[nt][0], b[nt][1]);
                        mma16816(acc[mt][2 * nt + 1], a[mt], b[nt][2], b[nt][3]);
                    }
            }
        }
        __syncthreads();

        // ---- stage D fragments to padded smem ----
#pragma unroll
        for (int mt = 0; mt < 2; mt++)
#pragma unroll
            for (int j = 0; j < 8; j++) {
                int row = wr * 32 + mt * 16 + (lane >> 2);
                int col = wc * 64 + j * 8 + 2 * (lane & 3);
                Dst[row * DSTRIDE + col]           = acc[mt][j][0];
                Dst[row * DSTRIDE + col + 1]       = acc[mt][j][1];
                Dst[(row + 8) * DSTRIDE + col]     = acc[mt][j][2];
                Dst[(row + 8) * DSTRIDE + col + 1] = acc[mt][j][3];
            }
        __syncthreads();

        if (mode == 0 && step == 0) {
            // PRE epilogue: bias + LN, write LN'd rows back to Dst
            float4 bb = __ldg((const float4*)&pre_b[lane * 4]);
#pragma unroll
            for (int r = 0; r < 16; r++) {
                int row = wid * 16 + r;
                float4 v = *(float4*)&Dst[row * DSTRIDE + lane * 4];
                v.x += bb.x; v.y += bb.y; v.z += bb.z; v.w += bb.w;
                float s1 = v.x + v.y + v.z + v.w;
                float s2 = v.x * v.x + v.y * v.y + v.z * v.z + v.w * v.w;
#pragma unroll
                for (int m = 16; m; m >>= 1) {
                    s1 += __shfl_xor_sync(0xffffffffu, s1, m);
                    s2 += __shfl_xor_sync(0xffffffffu, s2, m);
                }
                float mean = s1 * (1.0f / 128.0f);
                float var  = s2 * (1.0f / 128.0f) - mean * mean;
                float rstd = rsqrtf(var + 1e-5f);
                float4 o = make_float4((v.x - mean) * rstd, (v.y - mean) * rstd,
                                       (v.z - mean) * rstd, (v.w - mean) * rstd);
                *(float4*)&Dst[row * DSTRIDE + lane * 4] = o;
            }
            __syncthreads();
            // rebuild A image from LN'd Dst
#pragma unroll
            for (int it = 0; it < 8; it++) {
                int c = tid + it * 256;
                int row = c >> 4, kc = c & 15;
                float4 a = *(float4*)&Dst[row * DSTRIDE + kc * 8];
                float4 b = *(float4*)&Dst[row * DSTRIDE + kc * 8 + 4];
                float v[8] = {a.x, a.y, a.z, a.w, b.x, b.y, b.z, b.w};
                __nv_bfloat16 h8[8], l8[8];
#pragma unroll
                for (int j = 0; j < 8; j++) {
                    h8[j] = __float2bfloat16(v[j]);
                    l8[j] = __float2bfloat16(v[j] - __bfloat162float(h8[j]));
                }
                int off = soff(row, kc);
                *(uint4*)(sm + off) = *(uint4*)h8;
                *(uint4*)(sm + TILEB + off) = *(uint4*)l8;
            }
        } else if (mode == 0) {
            int iw = step - 1;
            const float* b1; const float* b2; float* out; float sc; int dg = 0;
            float sc_e = expf(init0[2]);
            float sc_v = expf(init0[3]);
            if (iw == 0)      { b1 = m1b; b2 = r0b; sc = sc_e; out = g_Q; }
            else if (iw == 1) { b1 = m2b; b2 = r1b; sc = sc_e; out = g_K; }
            else if (iw == 2) { b1 = m3b; b2 = r2b; sc = sc_v; out = g_V; }
            else              { b1 = m0b; b2 = 0;   sc = 0.f;  out = g_X2; dg = 1; }
            float4 bb = __ldg((const float4*)&b1[lane * 4]);
            if (b2) {
                float4 b2v = __ldg((const float4*)&b2[lane * 4]);
                bb.x += sc * b2v.x; bb.y += sc * b2v.y;
                bb.z += sc * b2v.z; bb.w += sc * b2v.w;
            }
#pragma unroll
            for (int r = 0; r < 16; r++) {
                int row = wid * 16 + r;
                int gr = r0 + row;
                if (gr >= n) continue;
                float4 v = *(float4*)&Dst[row * DSTRIDE + lane * 4];
                v.x += bb.x; v.y += bb.y; v.z += bb.z; v.w += bb.w;
                if (dg) { v.x = gelu1(v.x); v.y = gelu1(v.y);
                          v.z = gelu1(v.z); v.w = gelu1(v.w); }
                *(float4*)&out[gr * WIDTH + lane * 4] = v;
            }
        } else {
            float4 bb = __ldg((const float4*)&post_b[lane * 4]);
#pragma unroll
            for (int r = 0; r < 16; r++) {
                int row = wid * 16 + r;
                int gr = r0 + row;
                if (gr >= n) continue;
                float4 v = *(float4*)&Dst[row * DSTRIDE + lane * 4];
                float4 xv = __ldg((const float4*)&x[gr * WIDTH + lane * 4]);
                float4 o = make_float4(v.x + bb.x + xv.x, v.y + bb.y + xv.y,
                                       v.z + bb.z + xv.z, v.w + bb.w + xv.w);
                *(float4*)&dout[gr * WIDTH + lane * 4] = o;
            }
        }
        __syncthreads();
    }
}

// ============================================================================
// Edge phase: one warp per edge.
// Fast path (init0[0]==0): att is a constant -> no Q/K work at all.
// Slow path: full q.k attention (generic correctness).
// ============================================================================
__global__ void __launch_bounds__(256) k_edge(const int* __restrict__ ei,
                                              const int* __restrict__ ea,
                                              const float* __restrict__ init0, int e)
{
    int gw = blockIdx.x * 8 + (threadIdx.x >> 5);
    if (gw >= e) return;
    int lane = threadIdx.x & 31;

    float a0 = __ldg(&init0[0]);
    float b0 = __ldg(&init0[1]);

    int src = __ldg(ei + gw);
    int dst = __ldg(ei + e + gw);
    int4 a = __ldg((const int4*)ea + gw);
    int idx = a.x + 3 * a.y + 9 * a.z + 27 * a.w;

    const float4* T = (const float4*)g_T81;
    int c4 = lane << 2;
    float4 t2 = __ldg(&T[(idx * 3 + 2) * 32 + lane]);
    float4 vv = __ldg((const float4*)&g_V[src * WIDTH + c4]);

    float att;
    if (a0 == 0.0f) {
        att = __expf(b0);                       // constant attention
    } else {
        float4 t0 = __ldg(&T[(idx * 3 + 0) * 32 + lane]);
        float4 t1 = __ldg(&T[(idx * 3 + 1) * 32 + lane]);
        float4 qv = __ldg((const float4*)&g_Q[dst * WIDTH + c4]);
        float4 kv = __ldg((const float4*)&g_K[src * WIDTH + c4]);
        float s = (qv.x + t0.x) * (kv.x + t1.x) + (qv.y + t0.y) * (kv.y + t1.y)
                + (qv.z + t0.z) * (kv.z + t1.z) + (qv.w + t0.w) * (kv.w + t1.w);
#pragma unroll
        for (int m = 8; m; m >>= 1) s += __shfl_xor_sync(0xffffffffu, s, m);
        att = __expf(fmaf(s, a0 * 0.125f, b0));
    }

    float m0 = gelu_t(vv.x + t2.x) * att;
    float m1 = gelu_t(vv.y + t2.y) * att;
    float m2 = gelu_t(vv.z + t2.z) * att;
    float m3 = gelu_t(vv.w + t2.w) * att;

    float* dptr = &g_X2[dst * WIDTH + c4];
    asm volatile("red.global.add.v4.f32 [%0], {%1,%2,%3,%4};"
                 :: "l"(dptr), "f"(m0), "f"(m1), "f"(m2), "f"(m3) : "memory");
}

extern "C" void kernel_launch(void* const* d_in, const int* in_sizes, int n_in,
                              void* d_out, int out_size)
{
    const float* x        = (const float*)d_in[0];
    const int*   ei       = (const int*)  d_in[1];
    const int*   ea       = (const int*)  d_in[2];
    const float* pre_w    = (const float*)d_in[3];
    const float* pre_b    = (const float*)d_in[4];
    const float* msg0_w   = (const float*)d_in[5];
    const float* msg0_b   = (const float*)d_in[6];
    const float* msg1_w   = (const float*)d_in[7];
    const float* msg1_b   = (const float*)d_in[8];
    const float* msg2_w   = (const float*)d_in[9];
    const float* msg2_b   = (const float*)d_in[10];
    const float* msg3_w   = (const float*)d_in[11];
    const float* msg3_b   = (const float*)d_in[12];
    const float* remix0_w = (const float*)d_in[13];
    const float* remix0_b = (const float*)d_in[14];
    const float* remix1_w = (const float*)d_in[15];
    const float* remix1_b = (const float*)d_in[16];
    const float* remix2_w = (const float*)d_in[17];
    const float* remix2_b = (const float*)d_in[18];
    const float* post_w   = (const float*)d_in[19];
    const float* post_b   = (const float*)d_in[20];
    const float* emb0     = (const float*)d_in[21];
    const float* emb1     = (const float*)d_in[22];
    const float* emb2     = (const float*)d_in[23];
    const float* emb3     = (const float*)d_in[24];
    const float* einit    = (const float*)d_in[25];
    const float* init0    = (const float*)d_in[26];

    int n = in_sizes[0] / WIDTH;
    int e = in_sizes[1] / 2;
    int nt = (n + 127) / 128;

    static int smem_set = 0;
    if (!smem_set) {
        cudaFuncSetAttribute(k_mma, cudaFuncAttributeMaxDynamicSharedMemorySize, DSMEM);
        smem_set = 1;
    }

    k_prepw<<<48, 256>>>(pre_w, msg1_w, msg2_w, msg3_w, msg0_w, post_w);

    dim3 tg(3, 34);
    k_tables<<<tg, 128>>>(remix0_w, remix1_w, remix2_w, emb0, emb1, emb2, emb3, einit, init0);
    dim3 cg(3, 81);
    k_combine<<<cg, 128>>>();

    // PRE + QKVM fused (Q/K GEMMs skipped on device when init0[0]==0)
    k_mma<<<nt, 256, DSMEM>>>(0, x, pre_b, post_b, msg0_b, msg1_b, msg2_b, msg3_b,
                              remix0_b, remix1_b, remix2_b, init0, (float*)d_out, n);

    // edge aggregation
    k_edge<<<(e + 7) / 8, 256>>>(ei, ea, init0, e);

    // POST: out = x + X2 @ post_w + post_b
    k_mma<<<nt, 256, DSMEM>>>(2, x, pre_b, post_b, msg0_b, msg1_b, msg2_b, msg3_b,
                              remix0_b, remix1_b, remix2_b, init0, (float*)d_out, n);
}

// round 7
// speedup vs baseline: 1.5843x; 1.0445x over previous
#include <cuda_runtime.h>
#include <cuda_bf16.h>
#include <cuda_fp16.h>
#include <math.h>
#include <stdint.h>

#define WIDTH 128
#define NMAX  50176
#define TILEB 32768                       // one 128x128 bf16 tile image
#define DSTRIDE 132                       // staging row stride (floats)
#define DSMEM (4 * TILEB + 128 * DSTRIDE * 4)   // 198656 bytes

// ---- scratch (device globals) ----
__device__ float  g_Q [NMAX * WIDTH];
__device__ float  g_K [NMAX * WIDTH];
__device__ __half g_Vh[NMAX * WIDTH];
__device__ float  g_X2[NMAX * WIDTH];
__device__ float  g_T  [3 * 34 * WIDTH];
__device__ float  g_T81[81 * 3 * WIDTH];       // [idx][j][128]
__device__ unsigned char g_iW[6][2][TILEB];    // weight images (n x k), hi/lo
__device__ unsigned char g_iXh[392 * TILEB];   // xx image hi
__device__ unsigned char g_iXl[392 * TILEB];   // xx image lo

__device__ __forceinline__ float gelu1(float x) {
    return 0.5f * x * (1.0f + erff(x * 0.7071067811865475f));
}
__device__ __forceinline__ float gelu_t(float x) {
    float u = 0.7978845608028654f * fmaf(0.044715f * x, x * x, x);
    float t;
    asm("tanh.approx.f32 %0, %1;" : "=f"(t) : "f"(u));
    return 0.5f * x * (1.0f + t);
}

// XOR-swizzled offset for a 128-row x 16-chunk (16B chunks) bf16 tile.
__device__ __forceinline__ int soff(int row, int kc) {
    return row * 256 + ((kc ^ (row & 7)) << 4);
}
__device__ __forceinline__ uint32_t smem_u32(const void* p) {
    uint32_t a;
    asm("{ .reg .u64 t; cvta.to.shared.u64 t, %1; cvt.u32.u64 %0, t; }" : "=r"(a) : "l"(p));
    return a;
}
__device__ __forceinline__ void cpa16(uint32_t s, const void* g) {
    asm volatile("cp.async.ca.shared.global [%0], [%1], 16;" :: "r"(s), "l"(g));
}
__device__ __forceinline__ void cpa_wait() {
    asm volatile("cp.async.commit_group;");
    asm volatile("cp.async.wait_group 0;");
}
__device__ __forceinline__ void ldm4(uint32_t* r, uint32_t a) {
    asm volatile("ldmatrix.sync.aligned.m8n8.x4.shared.b16 {%0,%1,%2,%3}, [%4];"
                 : "=r"(r[0]), "=r"(r[1]), "=r"(r[2]), "=r"(r[3]) : "r"(a));
}
__device__ __forceinline__ void mma16816(float* c, const uint32_t* a, uint32_t b0, uint32_t b1) {
    asm volatile(
        "mma.sync.aligned.m16n8k16.row.col.f32.bf16.bf16.f32 "
        "{%0,%1,%2,%3}, {%4,%5,%6,%7}, {%8,%9}, {%0,%1,%2,%3};"
        : "+f"(c[0]), "+f"(c[1]), "+f"(c[2]), "+f"(c[3])
        : "r"(a[0]), "r"(a[1]), "r"(a[2]), "r"(a[3]), "r"(b0), "r"(b1));
}

// ============================================================================
// Tables
// ============================================================================
__global__ void k_tables(const float* __restrict__ r0w, const float* __restrict__ r1w,
                         const float* __restrict__ r2w,
                         const float* __restrict__ e0, const float* __restrict__ e1,
                         const float* __restrict__ e2, const float* __restrict__ e3,
                         const float* __restrict__ einit, const float* __restrict__ init0)
{
    int j = blockIdx.x, r = blockIdx.y, o = threadIdx.x;
    int c, lr;
    if (r < 6)       { c = 0; lr = r; }
    else if (r < 13) { c = 1; lr = r - 6; }
    else if (r < 16) { c = 2; lr = r - 13; }
    else             { c = 3; lr = r - 16; }
    const float* emb = (c == 0) ? e0 : (c == 1) ? e1 : (c == 2) ? e2 : e3;
    const float* rw  = (j == 0) ? r0w : (j == 1) ? r1w : r2w;

    __shared__ float er[64];
    if (o < 64) er[o] = emb[lr * 64 + o];
    __syncthreads();

    float s = 0.0f;
#pragma unroll
    for (int m = 0; m < 64; m++) s += er[m] * rw[m * WIDTH + o];

    float es = expf(einit[0]) + expf(einit[1]) + expf(einit[2]) + expf(einit[3]);
    float xw = expf(einit[c]) * rsqrtf(es);
    float sf = expf((j == 2) ? init0[3] : init0[2]);
    g_T[(j * 34 + r) * WIDTH + o] = s * xw * sf;
}

__global__ void k_combine()
{
    int j = blockIdx.x, i = blockIdx.y, o = threadIdx.x;
    int d0 = i % 3, d1 = (i / 3) % 3, d2 = (i / 9) % 3, d3 = i / 27;
    g_T81[(i * 3 + j) * WIDTH + o] =
        g_T[(j * 34 + d0) * WIDTH + o] + g_T[(j * 34 + 6 + d1) * WIDTH + o] +
        g_T[(j * 34 + 13 + d2) * WIDTH + o] + g_T[(j * 34 + 16 + d3) * WIDTH + o];
}

// ============================================================================
// Weight prep: Bt[n][k] = W[k][n], bf16 hi/lo, swizzled image.
// ============================================================================
__global__ void __launch_bounds__(256) k_prepw(const float* __restrict__ w0,
    const float* __restrict__ w1, const float* __restrict__ w2,
    const float* __restrict__ w3, const float* __restrict__ w4,
    const float* __restrict__ w5)
{
    int wi = blockIdx.x >> 3, sl = blockIdx.x & 7;
    const float* W = (wi == 0) ? w0 : (wi == 1) ? w1 : (wi == 2) ? w2
                   : (wi == 3) ? w3 : (wi == 4) ? w4 : w5;
    int nrow = sl * 16 + (threadIdx.x >> 4);
    int kc = threadIdx.x & 15;
    __nv_bfloat16 h8[8], l8[8];
#pragma unroll
    for (int j = 0; j < 8; j++) {
        float v = W[(kc * 8 + j) * WIDTH + nrow];   // transpose read
        h8[j] = __float2bfloat16(v);
        l8[j] = __float2bfloat16(v - __bfloat162float(h8[j]));
    }
    int off = soff(nrow, kc);
    *(uint4*)(g_iW[wi][0] + off) = *(uint4*)h8;
    *(uint4*)(g_iW[wi][1] + off) = *(uint4*)l8;
}

// ============================================================================
// mma.sync GEMM, 128x128 tile, fp32-accurate via bf16 hi/lo (3 passes).
// mode 0: PRE. A <- cvt(x). Epilogue: bias+LN -> write xx images (bf16 hi/lo).
// mode 1: one GEMM per CTA, blockIdx.y = step (0=Q,1=K,2=V,3=X2). A <- xx images.
//         Steps 0,1 self-retire when init0[0]==0 (att constant).
// mode 2: POST. A <- cvt(g_X2). Epilogue: bias + residual -> dout.
// ============================================================================
__global__ void __launch_bounds__(256, 1)
k_mma(int mode, const float* __restrict__ x,
      const float* __restrict__ pre_b, const float* __restrict__ post_b,
      const float* __restrict__ m0b, const float* __restrict__ m1b,
      const float* __restrict__ m2b, const float* __restrict__ m3b,
      const float* __restrict__ r0b, const float* __restrict__ r1b,
      const float* __restrict__ r2b,
      const float* __restrict__ init0, float* __restrict__ dout, int n)
{
    extern __shared__ unsigned char sm[];
    const uint32_t sbase = smem_u32(sm);
    const uint32_t sAh = sbase, sAl = sbase + TILEB;
    const uint32_t sBh = sbase + 2 * TILEB, sBl = sbase + 3 * TILEB;
    float* Dst = (float*)(sm + 4 * TILEB);

    const int tid = threadIdx.x;
    const int wid = tid >> 5, lane = tid & 31;
    const int wr = wid >> 1, wc = wid & 1;
    const int tile = blockIdx.x, r0 = tile * 128;
    const int step = blockIdx.y;

    if (mode == 1 && step < 2 && __ldg(&init0[0]) == 0.0f) return;  // fast path

    const int widx = (mode == 0) ? 0 : (mode == 2) ? 5 : (step + 1);

    // ---- W copy via cp.async ----
#pragma unroll
    for (int i = 0; i < 8; i++) {
        int idx = tid + i * 256;
        cpa16(sBh + idx * 16, g_iW[widx][0] + idx * 16);
        cpa16(sBl + idx * 16, g_iW[widx][1] + idx * 16);
    }

    // ---- A tile ----
    if (mode == 1) {
#pragma unroll
        for (int i = 0; i < 8; i++) {
            int idx = tid + i * 256;
            cpa16(sAh + idx * 16, g_iXh + tile * TILEB + idx * 16);
            cpa16(sAl + idx * 16, g_iXl + tile * TILEB + idx * 16);
        }
    } else {
        const float* Asrc = (mode == 0) ? x : g_X2;
#pragma unroll
        for (int it = 0; it < 8; it++) {
            int c = tid + it * 256;
            int row = c >> 4, kc = c & 15;
            int gr = r0 + row;
            float v[8];
            if (gr < n) {
                float4 a = *(const float4*)&Asrc[gr * WIDTH + kc * 8];
                float4 b = *(const float4*)&Asrc[gr * WIDTH + kc * 8 + 4];
                v[0] = a.x; v[1] = a.y; v[2] = a.z; v[3] = a.w;
                v[4] = b.x; v[5] = b.y; v[6] = b.z; v[7] = b.w;
            } else {
#pragma unroll
                for (int j = 0; j < 8; j++) v[j] = 0.0f;
            }
            __nv_bfloat16 h8[8], l8[8];
#pragma unroll
            for (int j = 0; j < 8; j++) {
                h8[j] = __float2bfloat16(v[j]);
                l8[j] = __float2bfloat16(v[j] - __bfloat162float(h8[j]));
            }
            int off = soff(row, kc);
            *(uint4*)(sm + off) = *(uint4*)h8;
            *(uint4*)(sm + TILEB + off) = *(uint4*)l8;
        }
    }
    cpa_wait();
    __syncthreads();

    // ---- mma: 3 hi/lo passes ----
    float acc[2][8][4];
#pragma unroll
    for (int i = 0; i < 2; i++)
#pragma unroll
        for (int j = 0; j < 8; j++)
#pragma unroll
            for (int q = 0; q < 4; q++) acc[i][j][q] = 0.0f;

#pragma unroll
    for (int pass = 0; pass < 3; pass++) {
        uint32_t Ab = (pass == 2) ? sAl : sAh;
        uint32_t Bb = (pass == 1) ? sBl : sBh;
#pragma unroll
        for (int kk = 0; kk < 8; kk++) {
            uint32_t a[2][4], b[4][4];
#pragma unroll
            for (int mt = 0; mt < 2; mt++) {
                int row = wr * 32 + mt * 16 + (lane & 15);
                int kc = 2 * kk + (lane >> 4);
                ldm4(a[mt], Ab + soff(row, kc));
            }
#pragma unroll
            for (int nt = 0; nt < 4; nt++) {
                int nn = wc * 64 + nt * 16 + (lane & 7) + ((lane >> 4) << 3);
                int kc = 2 * kk + ((lane >> 3) & 1);
                ldm4(b[nt], Bb + soff(nn, kc));
            }
#pragma unroll
            for (int mt = 0; mt < 2; mt++)
#pragma unroll
                for (int nt = 0; nt < 4; nt++) {
                    mma16816(acc[mt][2 * nt],     a[mt], b[nt][0], b[nt][1]);
                    mma16816(acc[mt][2 * nt + 1], a[mt], b[nt][2], b[nt][3]);
                }
        }
    }
    __syncthreads();

    // ---- stage D fragments to padded smem ----
#pragma unroll
    for (int mt = 0; mt < 2; mt++)
#pragma unroll
        for (int j = 0; j < 8; j++) {
            int row = wr * 32 + mt * 16 + (lane >> 2);
            int col = wc * 64 + j * 8 + 2 * (lane & 3);
            Dst[row * DSTRIDE + col]           = acc[mt][j][0];
            Dst[row * DSTRIDE + col + 1]       = acc[mt][j][1];
            Dst[(row + 8) * DSTRIDE + col]     = acc[mt][j][2];
            Dst[(row + 8) * DSTRIDE + col + 1] = acc[mt][j][3];
        }
    __syncthreads();

    if (mode == 0) {
        // PRE epilogue: bias + LN -> Dst, then write xx images
        float4 bb = __ldg((const float4*)&pre_b[lane * 4]);
#pragma unroll
        for (int r = 0; r < 16; r++) {
            int row = wid * 16 + r;
            float4 v = *(float4*)&Dst[row * DSTRIDE + lane * 4];
            v.x += bb.x; v.y += bb.y; v.z += bb.z; v.w += bb.w;
            float s1 = v.x + v.y + v.z + v.w;
            float s2 = v.x * v.x + v.y * v.y + v.z * v.z + v.w * v.w;
#pragma unroll
            for (int m = 16; m; m >>= 1) {
                s1 += __shfl_xor_sync(0xffffffffu, s1, m);
                s2 += __shfl_xor_sync(0xffffffffu, s2, m);
            }
            float mean = s1 * (1.0f / 128.0f);
            float var  = s2 * (1.0f / 128.0f) - mean * mean;
            float rstd = rsqrtf(var + 1e-5f);
            float4 o = make_float4((v.x - mean) * rstd, (v.y - mean) * rstd,
                                   (v.z - mean) * rstd, (v.w - mean) * rstd);
            *(float4*)&Dst[row * DSTRIDE + lane * 4] = o;
        }
        __syncthreads();
#pragma unroll
        for (int it = 0; it < 8; it++) {
            int c = tid + it * 256;
            int row = c >> 4, kc = c & 15;
            float4 a = *(float4*)&Dst[row * DSTRIDE + kc * 8];
            float4 b = *(float4*)&Dst[row * DSTRIDE + kc * 8 + 4];
            float v[8] = {a.x, a.y, a.z, a.w, b.x, b.y, b.z, b.w};
            __nv_bfloat16 h8[8], l8[8];
#pragma unroll
            for (int j = 0; j < 8; j++) {
                h8[j] = __float2bfloat16(v[j]);
                l8[j] = __float2bfloat16(v[j] - __bfloat162float(h8[j]));
            }
            int off = tile * TILEB + soff(row, kc);
            *(uint4*)(g_iXh + off) = *(uint4*)h8;
            *(uint4*)(g_iXl + off) = *(uint4*)l8;
        }
    } else if (mode == 1) {
        const float* b1; const float* b2; float sc;
        float sc_e = expf(__ldg(&init0[2]));
        float sc_v = expf(__ldg(&init0[3]));
        if (step == 0)      { b1 = m1b; b2 = r0b; sc = sc_e; }
        else if (step == 1) { b1 = m2b; b2 = r1b; sc = sc_e; }
        else if (step == 2) { b1 = m3b; b2 = r2b; sc = sc_v; }
        else                { b1 = m0b; b2 = 0;   sc = 0.f; }
        float4 bb = __ldg((const float4*)&b1[lane * 4]);
        if (b2) {
            float4 b2v = __ldg((const float4*)&b2[lane * 4]);
            bb.x += sc * b2v.x; bb.y += sc * b2v.y;
            bb.z += sc * b2v.z; bb.w += sc * b2v.w;
        }
#pragma unroll
        for (int r = 0; r < 16; r++) {
            int row = wid * 16 + r;
            int gr = r0 + row;
            if (gr >= n) continue;
            float4 v = *(float4*)&Dst[row * DSTRIDE + lane * 4];
            v.x += bb.x; v.y += bb.y; v.z += bb.z; v.w += bb.w;
            if (step == 0) {
                *(float4*)&g_Q[gr * WIDTH + lane * 4] = v;
            } else if (step == 1) {
                *(float4*)&g_K[gr * WIDTH + lane * 4] = v;
            } else if (step == 2) {
                __half h4[4] = {__float2half_rn(v.x), __float2half_rn(v.y),
                                __float2half_rn(v.z), __float2half_rn(v.w)};
                *(uint2*)&g_Vh[gr * WIDTH + lane * 4] = *(uint2*)h4;
            } else {
                v.x = gelu1(v.x); v.y = gelu1(v.y);
                v.z = gelu1(v.z); v.w = gelu1(v.w);
                *(float4*)&g_X2[gr * WIDTH + lane * 4] = v;
            }
        }
    } else {
        float4 bb = __ldg((const float4*)&post_b[lane * 4]);
#pragma unroll
        for (int r = 0; r < 16; r++) {
            int row = wid * 16 + r;
            int gr = r0 + row;
            if (gr >= n) continue;
            float4 v = *(float4*)&Dst[row * DSTRIDE + lane * 4];
            float4 xv = __ldg((const float4*)&x[gr * WIDTH + lane * 4]);
            float4 o = make_float4(v.x + bb.x + xv.x, v.y + bb.y + xv.y,
                                   v.z + bb.z + xv.z, v.w + bb.w + xv.w);
            *(float4*)&dout[gr * WIDTH + lane * 4] = o;
        }
    }
}

// ============================================================================
// Edge phase: one warp per edge. V in fp16.
// Fast path (init0[0]==0): att constant -> only V + table + red.
// ============================================================================
__global__ void __launch_bounds__(256) k_edge(const int* __restrict__ ei,
                                              const int* __restrict__ ea,
                                              const float* __restrict__ init0, int e)
{
    int gw = blockIdx.x * 8 + (threadIdx.x >> 5);
    if (gw >= e) return;
    int lane = threadIdx.x & 31;

    float a0 = __ldg(&init0[0]);
    float b0 = __ldg(&init0[1]);

    int src = __ldg(ei + gw);
    int dst = __ldg(ei + e + gw);
    int4 a = __ldg((const int4*)ea + gw);
    int idx = a.x + 3 * a.y + 9 * a.z + 27 * a.w;

    const float4* T = (const float4*)g_T81;
    int c4 = lane << 2;
    float4 t2 = __ldg(&T[(idx * 3 + 2) * 32 + lane]);
    uint2 vraw = __ldg((const uint2*)&g_Vh[src * WIDTH + c4]);
    float2 vlo = __half22float2(*(const __half2*)&vraw.x);
    float2 vhi = __half22float2(*(const __half2*)&vraw.y);

    float att;
    if (a0 == 0.0f) {
        att = __expf(b0);                       // constant attention
    } else {
        float4 t0 = __ldg(&T[(idx * 3 + 0) * 32 + lane]);
        float4 t1 = __ldg(&T[(idx * 3 + 1) * 32 + lane]);
        float4 qv = __ldg((const float4*)&g_Q[dst * WIDTH + c4]);
        float4 kv = __ldg((const float4*)&g_K[src * WIDTH + c4]);
        float s = (qv.x + t0.x) * (kv.x + t1.x) + (qv.y + t0.y) * (kv.y + t1.y)
                + (qv.z + t0.z) * (kv.z + t1.z) + (qv.w + t0.w) * (kv.w + t1.w);
#pragma unroll
        for (int m = 8; m; m >>= 1) s += __shfl_xor_sync(0xffffffffu, s, m);
        att = __expf(fmaf(s, a0 * 0.125f, b0));
    }

    float m0 = gelu_t(vlo.x + t2.x) * att;
    float m1 = gelu_t(vlo.y + t2.y) * att;
    float m2 = gelu_t(vhi.x + t2.z) * att;
    float m3 = gelu_t(vhi.y + t2.w) * att;

    float* dptr = &g_X2[dst * WIDTH + c4];
    asm volatile("red.global.add.v4.f32 [%0], {%1,%2,%3,%4};"
                 :: "l"(dptr), "f"(m0), "f"(m1), "f"(m2), "f"(m3) : "memory");
}

extern "C" void kernel_launch(void* const* d_in, const int* in_sizes, int n_in,
                              void* d_out, int out_size)
{
    const float* x        = (const float*)d_in[0];
    const int*   ei       = (const int*)  d_in[1];
    const int*   ea       = (const int*)  d_in[2];
    const float* pre_w    = (const float*)d_in[3];
    const float* pre_b    = (const float*)d_in[4];
    const float* msg0_w   = (const float*)d_in[5];
    const float* msg0_b   = (const float*)d_in[6];
    const float* msg1_w   = (const float*)d_in[7];
    const float* msg1_b   = (const float*)d_in[8];
    const float* msg2_w   = (const float*)d_in[9];
    const float* msg2_b   = (const float*)d_in[10];
    const float* msg3_w   = (const float*)d_in[11];
    const float* msg3_b   = (const float*)d_in[12];
    const float* remix0_w = (const float*)d_in[13];
    const float* remix0_b = (const float*)d_in[14];
    const float* remix1_w = (const float*)d_in[15];
    const float* remix1_b = (const float*)d_in[16];
    const float* remix2_w = (const float*)d_in[17];
    const float* remix2_b = (const float*)d_in[18];
    const float* post_w   = (const float*)d_in[19];
    const float* post_b   = (const float*)d_in[20];
    const float* emb0     = (const float*)d_in[21];
    const float* emb1     = (const float*)d_in[22];
    const float* emb2     = (const float*)d_in[23];
    const float* emb3     = (const float*)d_in[24];
    const float* einit    = (const float*)d_in[25];
    const float* init0    = (const float*)d_in[26];

    int n = in_sizes[0] / WIDTH;
    int e = in_sizes[1] / 2;
    int nt = (n + 127) / 128;

    static int smem_set = 0;
    if (!smem_set) {
        cudaFuncSetAttribute(k_mma, cudaFuncAttributeMaxDynamicSharedMemorySize, DSMEM);
        smem_set = 1;
    }

    k_prepw<<<48, 256>>>(pre_w, msg1_w, msg2_w, msg3_w, msg0_w, post_w);

    dim3 tg(3, 34);
    k_tables<<<tg, 128>>>(remix0_w, remix1_w, remix2_w, emb0, emb1, emb2, emb3, einit, init0);
    dim3 cg(3, 81);
    k_combine<<<cg, 128>>>();

    // PRE: xx images
    k_mma<<<nt, 256, DSMEM>>>(0, x, pre_b, post_b, msg0_b, msg1_b, msg2_b, msg3_b,
                              remix0_b, remix1_b, remix2_b, init0, (float*)d_out, n);

    // QKVM: one GEMM per CTA (Q/K CTAs self-retire when init0[0]==0)
    dim3 qg(nt, 4);
    k_mma<<<qg, 256, DSMEM>>>(1, x, pre_b, post_b, msg0_b, msg1_b, msg2_b, msg3_b,
                              remix0_b, remix1_b, remix2_b, init0, (float*)d_out, n);

    // edge aggregation
    k_edge<<<(e + 7) / 8, 256>>>(ei, ea, init0, e);

    // POST: out = x + X2 @ post_w + post_b
    k_mma<<<nt, 256, DSMEM>>>(2, x, pre_b, post_b, msg0_b, msg1_b, msg2_b, msg3_b,
                              remix0_b, remix1_b, remix2_b, init0, (float*)d_out, n);
}

// round 8
// speedup vs baseline: 1.6081x; 1.0150x over previous
#include <cuda_runtime.h>
#include <cuda_bf16.h>
#include <cuda_fp16.h>
#include <math.h>
#include <stdint.h>

#define WIDTH 128
#define NMAX  50176
#define EMAX  512000
#define TILEB 32768                       // one 128x128 bf16 tile image
#define DSTRIDE 132                       // staging row stride (floats)
#define DSMEM (4 * TILEB + 128 * DSTRIDE * 4)   // 198656 bytes

// ---- scratch (device globals) ----
__device__ float  g_Q [NMAX * WIDTH];
__device__ float  g_K [NMAX * WIDTH];
__device__ __half g_Vh[NMAX * WIDTH];
__device__ float  g_X2[NMAX * WIDTH];
__device__ float  g_T  [3 * 34 * WIDTH];
__device__ float  g_T81[81 * 3 * WIDTH];       // [idx][j][128]
__device__ unsigned char g_iW[6][2][TILEB];    // weight images (n x k), hi/lo
__device__ unsigned char g_iXh[392 * TILEB];   // xx image hi
__device__ unsigned char g_iXl[392 * TILEB];   // xx image lo
__device__ int g_cnt [NMAX];
__device__ int g_cur [NMAX];
__device__ int g_base[NMAX + 1];
__device__ int g_esrc[EMAX];
__device__ int g_eidx[EMAX];

__device__ __forceinline__ float gelu1(float x) {
    return 0.5f * x * (1.0f + erff(x * 0.7071067811865475f));
}
__device__ __forceinline__ float gelu_t(float x) {
    float u = 0.7978845608028654f * fmaf(0.044715f * x, x * x, x);
    float t;
    asm("tanh.approx.f32 %0, %1;" : "=f"(t) : "f"(u));
    return 0.5f * x * (1.0f + t);
}

// XOR-swizzled offset for a 128-row x 16-chunk (16B chunks) bf16 tile.
__device__ __forceinline__ int soff(int row, int kc) {
    return row * 256 + ((kc ^ (row & 7)) << 4);
}
__device__ __forceinline__ uint32_t smem_u32(const void* p) {
    uint32_t a;
    asm("{ .reg .u64 t; cvta.to.shared.u64 t, %1; cvt.u32.u64 %0, t; }" : "=r"(a) : "l"(p));
    return a;
}
__device__ __forceinline__ void cpa16(uint32_t s, const void* g) {
    asm volatile("cp.async.ca.shared.global [%0], [%1], 16;" :: "r"(s), "l"(g));
}
__device__ __forceinline__ void cpa_wait() {
    asm volatile("cp.async.commit_group;");
    asm volatile("cp.async.wait_group 0;");
}
__device__ __forceinline__ void ldm4(uint32_t* r, uint32_t a) {
    asm volatile("ldmatrix.sync.aligned.m8n8.x4.shared.b16 {%0,%1,%2,%3}, [%4];"
                 : "=r"(r[0]), "=r"(r[1]), "=r"(r[2]), "=r"(r[3]) : "r"(a));
}
__device__ __forceinline__ void mma16816(float* c, const uint32_t* a, uint32_t b0, uint32_t b1) {
    asm volatile(
        "mma.sync.aligned.m16n8k16.row.col.f32.bf16.bf16.f32 "
        "{%0,%1,%2,%3}, {%4,%5,%6,%7}, {%8,%9}, {%0,%1,%2,%3};"
        : "+f"(c[0]), "+f"(c[1]), "+f"(c[2]), "+f"(c[3])
        : "r"(a[0]), "r"(a[1]), "r"(a[2]), "r"(a[3]), "r"(b0), "r"(b1));
}

// ============================================================================
// Tables
// ============================================================================
__global__ void k_tables(const float* __restrict__ r0w, const float* __restrict__ r1w,
                         const float* __restrict__ r2w,
                         const float* __restrict__ e0, const float* __restrict__ e1,
                         const float* __restrict__ e2, const float* __restrict__ e3,
                         const float* __restrict__ einit, const float* __restrict__ init0)
{
    int j = blockIdx.x, r = blockIdx.y, o = threadIdx.x;
    int c, lr;
    if (r < 6)       { c = 0; lr = r; }
    else if (r < 13) { c = 1; lr = r - 6; }
    else if (r < 16) { c = 2; lr = r - 13; }
    else             { c = 3; lr = r - 16; }
    const float* emb = (c == 0) ? e0 : (c == 1) ? e1 : (c == 2) ? e2 : e3;
    const float* rw  = (j == 0) ? r0w : (j == 1) ? r1w : r2w;

    __shared__ float er[64];
    if (o < 64) er[o] = emb[lr * 64 + o];
    __syncthreads();

    float s = 0.0f;
#pragma unroll
    for (int m = 0; m < 64; m++) s += er[m] * rw[m * WIDTH + o];

    float es = expf(einit[0]) + expf(einit[1]) + expf(einit[2]) + expf(einit[3]);
    float xw = expf(einit[c]) * rsqrtf(es);
    float sf = expf((j == 2) ? init0[3] : init0[2]);
    g_T[(j * 34 + r) * WIDTH + o] = s * xw * sf;
}

__global__ void k_combine()
{
    int j = blockIdx.x, i = blockIdx.y, o = threadIdx.x;
    int d0 = i % 3, d1 = (i / 3) % 3, d2 = (i / 9) % 3, d3 = i / 27;
    g_T81[(i * 3 + j) * WIDTH + o] =
        g_T[(j * 34 + d0) * WIDTH + o] + g_T[(j * 34 + 6 + d1) * WIDTH + o] +
        g_T[(j * 34 + 13 + d2) * WIDTH + o] + g_T[(j * 34 + 16 + d3) * WIDTH + o];
}

// ============================================================================
// CSR build: zero -> histogram -> scan -> scatter
// ============================================================================
__global__ void k_zero(int n)
{
    int i = blockIdx.x * blockDim.x + threadIdx.x;
    if (i < n) { g_cnt[i] = 0; g_cur[i] = 0; }
}
__global__ void k_hist(const int* __restrict__ ei, int e)
{
    for (int i = blockIdx.x * blockDim.x + threadIdx.x; i < e; i += gridDim.x * blockDim.x)
        atomicAdd(&g_cnt[ei[e + i]], 1);
}
__global__ void __launch_bounds__(1024) k_scan(int n, int e)
{
    __shared__ int sp[1024];
    int t = threadIdx.x;
    int chunk = (n + 1023) >> 10;
    int lo = t * chunk, hi = min(lo + chunk, n);
    int s = 0;
    for (int i = lo; i < hi; i++) s += g_cnt[i];
    sp[t] = s;
    __syncthreads();
    for (int d = 1; d < 1024; d <<= 1) {
        int v = (t >= d) ? sp[t - d] : 0;
        __syncthreads();
        if (t >= d) sp[t] += v;
        __syncthreads();
    }
    int run = (t > 0) ? sp[t - 1] : 0;
    for (int i = lo; i < hi; i++) { int c = g_cnt[i]; g_base[i] = run; run += c; }
    if (t == 0) g_base[n] = e;
}
__global__ void k_scatter(const int* __restrict__ ei, const int* __restrict__ ea, int e)
{
    for (int i = blockIdx.x * blockDim.x + threadIdx.x; i < e; i += gridDim.x * blockDim.x) {
        int dst = ei[e + i];
        int4 a = __ldg((const int4*)ea + i);
        int idx = a.x + 3 * a.y + 9 * a.z + 27 * a.w;
        int pos = g_base[dst] + atomicAdd(&g_cur[dst], 1);
        g_esrc[pos] = ei[i];
        g_eidx[pos] = idx;
    }
}

// ============================================================================
// Weight prep: Bt[n][k] = W[k][n], bf16 hi/lo, swizzled image.
// ============================================================================
__global__ void __launch_bounds__(256) k_prepw(const float* __restrict__ w0,
    const float* __restrict__ w1, const float* __restrict__ w2,
    const float* __restrict__ w3, const float* __restrict__ w4,
    const float* __restrict__ w5)
{
    int wi = blockIdx.x >> 3, sl = blockIdx.x & 7;
    const float* W = (wi == 0) ? w0 : (wi == 1) ? w1 : (wi == 2) ? w2
                   : (wi == 3) ? w3 : (wi == 4) ? w4 : w5;
    int nrow = sl * 16 + (threadIdx.x >> 4);
    int kc = threadIdx.x & 15;
    __nv_bfloat16 h8[8], l8[8];
#pragma unroll
    for (int j = 0; j < 8; j++) {
        float v = W[(kc * 8 + j) * WIDTH + nrow];   // transpose read
        h8[j] = __float2bfloat16(v);
        l8[j] = __float2bfloat16(v - __bfloat162float(h8[j]));
    }
    int off = soff(nrow, kc);
    *(uint4*)(g_iW[wi][0] + off) = *(uint4*)h8;
    *(uint4*)(g_iW[wi][1] + off) = *(uint4*)l8;
}

// ============================================================================
// mma.sync GEMM, 128x128 tile, fp32-accurate via bf16 hi/lo (3 passes).
// 512 threads, 4x4 warp grid, 32x32 per warp.
// mode 0: PRE -> xx images. mode 1: blockIdx.y=step (0=Q,1=K,2=V,3=X2),
//         steps 0,1 self-retire when init0[0]==0. mode 2: POST -> dout.
// ============================================================================
__global__ void __launch_bounds__(512, 1)
k_mma(int mode, const float* __restrict__ x,
      const float* __restrict__ pre_b, const float* __restrict__ post_b,
      const float* __restrict__ m0b, const float* __restrict__ m1b,
      const float* __restrict__ m2b, const float* __restrict__ m3b,
      const float* __restrict__ r0b, const float* __restrict__ r1b,
      const float* __restrict__ r2b,
      const float* __restrict__ init0, float* __restrict__ dout, int n)
{
    extern __shared__ unsigned char sm[];
    const uint32_t sbase = smem_u32(sm);
    const uint32_t sAh = sbase, sAl = sbase + TILEB;
    const uint32_t sBh = sbase + 2 * TILEB, sBl = sbase + 3 * TILEB;
    float* Dst = (float*)(sm + 4 * TILEB);

    const int tid = threadIdx.x;
    const int wid = tid >> 5, lane = tid & 31;
    const int wr = wid >> 2, wc = wid & 3;
    const int tile = blockIdx.x, r0 = tile * 128;
    const int step = blockIdx.y;

    if (mode == 1 && step < 2 && __ldg(&init0[0]) == 0.0f) return;  // fast path

    const int widx = (mode == 0) ? 0 : (mode == 2) ? 5 : (step + 1);

    // ---- W copy via cp.async ----
#pragma unroll
    for (int i = 0; i < 4; i++) {
        int idx = tid + i * 512;
        cpa16(sBh + idx * 16, g_iW[widx][0] + idx * 16);
        cpa16(sBl + idx * 16, g_iW[widx][1] + idx * 16);
    }

    // ---- A tile ----
    if (mode == 1) {
#pragma unroll
        for (int i = 0; i < 4; i++) {
            int idx = tid + i * 512;
            cpa16(sAh + idx * 16, g_iXh + tile * TILEB + idx * 16);
            cpa16(sAl + idx * 16, g_iXl + tile * TILEB + idx * 16);
        }
    } else {
        const float* Asrc = (mode == 0) ? x : g_X2;
#pragma unroll
        for (int it = 0; it < 4; it++) {
            int c = tid + it * 512;
            int row = c >> 4, kc = c & 15;
            int gr = r0 + row;
            float v[8];
            if (gr < n) {
                float4 a = *(const float4*)&Asrc[gr * WIDTH + kc * 8];
                float4 b = *(const float4*)&Asrc[gr * WIDTH + kc * 8 + 4];
                v[0] = a.x; v[1] = a.y; v[2] = a.z; v[3] = a.w;
                v[4] = b.x; v[5] = b.y; v[6] = b.z; v[7] = b.w;
            } else {
#pragma unroll
                for (int j = 0; j < 8; j++) v[j] = 0.0f;
            }
            __nv_bfloat16 h8[8], l8[8];
#pragma unroll
            for (int j = 0; j < 8; j++) {
                h8[j] = __float2bfloat16(v[j]);
                l8[j] = __float2bfloat16(v[j] - __bfloat162float(h8[j]));
            }
            int off = soff(row, kc);
            *(uint4*)(sm + off) = *(uint4*)h8;
            *(uint4*)(sm + TILEB + off) = *(uint4*)l8;
        }
    }
    cpa_wait();
    __syncthreads();

    // ---- mma: 3 hi/lo passes, each warp 32x32 ----
    float acc[2][4][4];
#pragma unroll
    for (int i = 0; i < 2; i++)
#pragma unroll
        for (int j = 0; j < 4; j++)
#pragma unroll
            for (int q = 0; q < 4; q++) acc[i][j][q] = 0.0f;

#pragma unroll
    for (int pass = 0; pass < 3; pass++) {
        uint32_t Ab = (pass == 2) ? sAl : sAh;
        uint32_t Bb = (pass == 1) ? sBl : sBh;
#pragma unroll
        for (int kk = 0; kk < 8; kk++) {
            uint32_t a[2][4], b[2][4];
#pragma unroll
            for (int mt = 0; mt < 2; mt++) {
                int row = wr * 32 + mt * 16 + (lane & 15);
                int kc = 2 * kk + (lane >> 4);
                ldm4(a[mt], Ab + soff(row, kc));
            }
#pragma unroll
            for (int nt = 0; nt < 2; nt++) {
                int nn = wc * 32 + nt * 16 + (lane & 7) + ((lane >> 4) << 3);
                int kc = 2 * kk + ((lane >> 3) & 1);
                ldm4(b[nt], Bb + soff(nn, kc));
            }
#pragma unroll
            for (int mt = 0; mt < 2; mt++)
#pragma unroll
                for (int nt = 0; nt < 2; nt++) {
                    mma16816(acc[mt][2 * nt],     a[mt], b[nt][0], b[nt][1]);
                    mma16816(acc[mt][2 * nt + 1], a[mt], b[nt][2], b[nt][3]);
                }
        }
    }
    __syncthreads();

    // ---- stage D fragments to padded smem ----
#pragma unroll
    for (int mt = 0; mt < 2; mt++)
#pragma unroll
        for (int j = 0; j < 4; j++) {
            int row = wr * 32 + mt * 16 + (lane >> 2);
            int col = wc * 32 + j * 8 + 2 * (lane & 3);
            Dst[row * DSTRIDE + col]           = acc[mt][j][0];
            Dst[row * DSTRIDE + col + 1]       = acc[mt][j][1];
            Dst[(row + 8) * DSTRIDE + col]     = acc[mt][j][2];
            Dst[(row + 8) * DSTRIDE + col + 1] = acc[mt][j][3];
        }
    __syncthreads();

    if (mode == 0) {
        // PRE epilogue: bias + LN -> Dst, then write xx images
        float4 bb = __ldg((const float4*)&pre_b[lane * 4]);
#pragma unroll
        for (int r = 0; r < 8; r++) {
            int row = wid * 8 + r;
            float4 v = *(float4*)&Dst[row * DSTRIDE + lane * 4];
            v.x += bb.x; v.y += bb.y; v.z += bb.z; v.w += bb.w;
            float s1 = v.x + v.y + v.z + v.w;
            float s2 = v.x * v.x + v.y * v.y + v.z * v.z + v.w * v.w;
#pragma unroll
            for (int m = 16; m; m >>= 1) {
                s1 += __shfl_xor_sync(0xffffffffu, s1, m);
                s2 += __shfl_xor_sync(0xffffffffu, s2, m);
            }
            float mean = s1 * (1.0f / 128.0f);
            float var  = s2 * (1.0f / 128.0f) - mean * mean;
            float rstd = rsqrtf(var + 1e-5f);
            float4 o = make_float4((v.x - mean) * rstd, (v.y - mean) * rstd,
                                   (v.z - mean) * rstd, (v.w - mean) * rstd);
            *(float4*)&Dst[row * DSTRIDE + lane * 4] = o;
        }
        __syncthreads();
#pragma unroll
        for (int it = 0; it < 4; it++) {
            int c = tid + it * 512;
            int row = c >> 4, kc = c & 15;
            float4 a = *(float4*)&Dst[row * DSTRIDE + kc * 8];
            float4 b = *(float4*)&Dst[row * DSTRIDE + kc * 8 + 4];
            float v[8] = {a.x, a.y, a.z, a.w, b.x, b.y, b.z, b.w};
            __nv_bfloat16 h8[8], l8[8];
#pragma unroll
            for (int j = 0; j < 8; j++) {
                h8[j] = __float2bfloat16(v[j]);
                l8[j] = __float2bfloat16(v[j] - __bfloat162float(h8[j]));
            }
            int off = tile * TILEB + soff(row, kc);
            *(uint4*)(g_iXh + off) = *(uint4*)h8;
            *(uint4*)(g_iXl + off) = *(uint4*)l8;
        }
    } else if (mode == 1) {
        const float* b1; const float* b2; float sc;
        float sc_e = expf(__ldg(&init0[2]));
        float sc_v = expf(__ldg(&init0[3]));
        if (step == 0)      { b1 = m1b; b2 = r0b; sc = sc_e; }
        else if (step == 1) { b1 = m2b; b2 = r1b; sc = sc_e; }
        else if (step == 2) { b1 = m3b; b2 = r2b; sc = sc_v; }
        else                { b1 = m0b; b2 = 0;   sc = 0.f; }
        float4 bb = __ldg((const float4*)&b1[lane * 4]);
        if (b2) {
            float4 b2v = __ldg((const float4*)&b2[lane * 4]);
            bb.x += sc * b2v.x; bb.y += sc * b2v.y;
            bb.z += sc * b2v.z; bb.w += sc * b2v.w;
        }
#pragma unroll
        for (int r = 0; r < 8; r++) {
            int row = wid * 8 + r;
            int gr = r0 + row;
            if (gr >= n) continue;
            float4 v = *(float4*)&Dst[row * DSTRIDE + lane * 4];
            v.x += bb.x; v.y += bb.y; v.z += bb.z; v.w += bb.w;
            if (step == 0) {
                *(float4*)&g_Q[gr * WIDTH + lane * 4] = v;
            } else if (step == 1) {
                *(float4*)&g_K[gr * WIDTH + lane * 4] = v;
            } else if (step == 2) {
                __half h4[4] = {__float2half_rn(v.x), __float2half_rn(v.y),
                                __float2half_rn(v.z), __float2half_rn(v.w)};
                *(uint2*)&g_Vh[gr * WIDTH + lane * 4] = *(uint2*)h4;
            } else {
                v.x = gelu1(v.x); v.y = gelu1(v.y);
                v.z = gelu1(v.z); v.w = gelu1(v.w);
                *(float4*)&g_X2[gr * WIDTH + lane * 4] = v;
            }
        }
    } else {
        float4 bb = __ldg((const float4*)&post_b[lane * 4]);
#pragma unroll
        for (int r = 0; r < 8; r++) {
            int row = wid * 8 + r;
            int gr = r0 + row;
            if (gr >= n) continue;
            float4 v = *(float4*)&Dst[row * DSTRIDE + lane * 4];
            float4 xv = __ldg((const float4*)&x[gr * WIDTH + lane * 4]);
            float4 o = make_float4(v.x + bb.x + xv.x, v.y + bb.y + xv.y,
                                   v.z + bb.z + xv.z, v.w + bb.w + xv.w);
            *(float4*)&dout[gr * WIDTH + lane * 4] = o;
        }
    }
}

// ============================================================================
// Edge phase: one warp per destination node (CSR). V in fp16, no atomics.
// Fast path (init0[0]==0): att constant, factored out of the sum.
// ============================================================================
__global__ void __launch_bounds__(256) k_edgec(const float* __restrict__ init0, int n)
{
    int v = blockIdx.x * 8 + (threadIdx.x >> 5);
    if (v >= n) return;
    int lane = threadIdx.x & 31;
    int b0 = g_base[v], b1 = g_base[v + 1];
    if (b0 == b1) return;

    float a0 = __ldg(&init0[0]);
    float bb = __ldg(&init0[1]);
    int c4 = lane << 2;
    const float4* T = (const float4*)g_T81;
    float4 acc = make_float4(0.f, 0.f, 0.f, 0.f);

    if (a0 == 0.0f) {
        for (int j = b0; j < b1; j++) {
            int src = __ldg(&g_esrc[j]);
            int idx = __ldg(&g_eidx[j]);
            float4 t2 = __ldg(&T[(idx * 3 + 2) * 32 + lane]);
            uint2 vraw = __ldg((const uint2*)&g_Vh[src * WIDTH + c4]);
            float2 vlo = __half22float2(*(const __half2*)&vraw.x);
            float2 vhi = __half22float2(*(const __half2*)&vraw.y);
            acc.x += gelu_t(vlo.x + t2.x);
            acc.y += gelu_t(vlo.y + t2.y);
            acc.z += gelu_t(vhi.x + t2.z);
            acc.w += gelu_t(vhi.y + t2.w);
        }
        float att = __expf(bb);
        acc.x *= att; acc.y *= att; acc.z *= att; acc.w *= att;
    } else {
        float4 Qv = *(const float4*)&g_Q[v * WIDTH + c4];
        float sA = a0 * 0.125f;
        for (int j = b0; j < b1; j++) {
            int src = __ldg(&g_esrc[j]);
            int idx = __ldg(&g_eidx[j]);
            float4 t0 = __ldg(&T[(idx * 3 + 0) * 32 + lane]);
            float4 t1 = __ldg(&T[(idx * 3 + 1) * 32 + lane]);
            float4 t2 = __ldg(&T[(idx * 3 + 2) * 32 + lane]);
            float4 kv = __ldg((const float4*)&g_K[src * WIDTH + c4]);
            uint2 vraw = __ldg((const uint2*)&g_Vh[src * WIDTH + c4]);
            float2 vlo = __half22float2(*(const __half2*)&vraw.x);
            float2 vhi = __half22float2(*(const __half2*)&vraw.y);
            float s = (Qv.x + t0.x) * (kv.x + t1.x) + (Qv.y + t0.y) * (kv.y + t1.y)
                    + (Qv.z + t0.z) * (kv.z + t1.z) + (Qv.w + t0.w) * (kv.w + t1.w);
#pragma unroll
            for (int m = 8; m; m >>= 1) s += __shfl_xor_sync(0xffffffffu, s, m);
            float att = __expf(fmaf(s, sA, bb));
            acc.x = fmaf(gelu_t(vlo.x + t2.x), att, acc.x);
            acc.y = fmaf(gelu_t(vlo.y + t2.y), att, acc.y);
            acc.z = fmaf(gelu_t(vhi.x + t2.z), att, acc.z);
            acc.w = fmaf(gelu_t(vhi.y + t2.w), att, acc.w);
        }
    }

    float* xp = &g_X2[v * WIDTH + c4];
    float4 cur = *(float4*)xp;
    cur.x += acc.x; cur.y += acc.y; cur.z += acc.z; cur.w += acc.w;
    *(float4*)xp = cur;
}

extern "C" void kernel_launch(void* const* d_in, const int* in_sizes, int n_in,
                              void* d_out, int out_size)
{
    const float* x        = (const float*)d_in[0];
    const int*   ei       = (const int*)  d_in[1];
    const int*   ea       = (const int*)  d_in[2];
    const float* pre_w    = (const float*)d_in[3];
    const float* pre_b    = (const float*)d_in[4];
    const float* msg0_w   = (const float*)d_in[5];
    const float* msg0_b   = (const float*)d_in[6];
    const float* msg1_w   = (const float*)d_in[7];
    const float* msg1_b   = (const float*)d_in[8];
    const float* msg2_w   = (const float*)d_in[9];
    const float* msg2_b   = (const float*)d_in[10];
    const float* msg3_w   = (const float*)d_in[11];
    const float* msg3_b   = (const float*)d_in[12];
    const float* remix0_w = (const float*)d_in[13];
    const float* remix0_b = (const float*)d_in[14];
    const float* remix1_w = (const float*)d_in[15];
    const float* remix1_b = (const float*)d_in[16];
    const float* remix2_w = (const float*)d_in[17];
    const float* remix2_b = (const float*)d_in[18];
    const float* post_w   = (const float*)d_in[19];
    const float* post_b   = (const float*)d_in[20];
    const float* emb0     = (const float*)d_in[21];
    const float* emb1     = (const float*)d_in[22];
    const float* emb2     = (const float*)d_in[23];
    const float* emb3     = (const float*)d_in[24];
    const float* einit    = (const float*)d_in[25];
    const float* init0    = (const float*)d_in[26];

    int n = in_sizes[0] / WIDTH;
    int e = in_sizes[1] / 2;
    int nt = (n + 127) / 128;

    static cudaStream_t s2 = 0;
    static cudaEvent_t ev0 = 0, ev1 = 0;
    if (!s2) {
        cudaFuncSetAttribute(k_mma, cudaFuncAttributeMaxDynamicSharedMemorySize, DSMEM);
        cudaStreamCreateWithFlags(&s2, cudaStreamNonBlocking);
        cudaEventCreateWithFlags(&ev0, cudaEventDisableTiming);
        cudaEventCreateWithFlags(&ev1, cudaEventDisableTiming);
    }

    // fork side stream: tables + CSR build (independent of GEMM phase)
    cudaEventRecord(ev0, 0);
    cudaStreamWaitEvent(s2, ev0, 0);

    dim3 tg(3, 34);
    k_tables<<<tg, 128, 0, s2>>>(remix0_w, remix1_w, remix2_w,
                                 emb0, emb1, emb2, emb3, einit, init0);
    dim3 cg(3, 81);
    k_combine<<<cg, 128, 0, s2>>>();
    k_zero<<<(n + 255) / 256, 256, 0, s2>>>(n);
    k_hist<<<512, 256, 0, s2>>>(ei, e);
    k_scan<<<1, 1024, 0, s2>>>(n, e);
    k_scatter<<<512, 256, 0, s2>>>(ei, ea, e);
    cudaEventRecord(ev1, s2);

    // main stream: GEMM phase
    k_prepw<<<48, 256>>>(pre_w, msg1_w, msg2_w, msg3_w, msg0_w, post_w);

    k_mma<<<nt, 512, DSMEM>>>(0, x, pre_b, post_b, msg0_b, msg1_b, msg2_b, msg3_b,
                              remix0_b, remix1_b, remix2_b, init0, (float*)d_out, n);

    dim3 qg(nt, 4);
    k_mma<<<qg, 512, DSMEM>>>(1, x, pre_b, post_b, msg0_b, msg1_b, msg2_b, msg3_b,
                              remix0_b, remix1_b, remix2_b, init0, (float*)d_out, n);

    // join side stream, then edge aggregation
    cudaStreamWaitEvent(0, ev1, 0);
    k_edgec<<<(n + 7) / 8, 256>>>(init0, n);

    // POST: out = x + X2 @ post_w + post_b
    k_mma<<<nt, 512, DSMEM>>>(2, x, pre_b, post_b, msg0_b, msg1_b, msg2_b, msg3_b,
                              remix0_b, remix1_b, remix2_b, init0, (float*)d_out, n);
}